// round 1
// baseline (speedup 1.0000x reference)
#include <cuda_runtime.h>
#include <cuda_bf16.h>

// Problem shapes (fixed by the dataset)
#define Bn 8192
#define Mn 64
#define Dn 256

// Scratch for r = attn @ mem  (8 MB). Device global => allowed under _HX_ENFORCE.
__device__ float g_r[(size_t)Bn * Dn];

// ---------------------------------------------------------------------------
// Kernel 1: per-sample masked attention over ragged memory.
// One CTA per b. Stage mem[b] (64 KB) in shared, single HBM read.
// ---------------------------------------------------------------------------
__global__ __launch_bounds__(256) void attn_kernel(
    const float* __restrict__ h,
    const float* __restrict__ mem,
    const int*   __restrict__ lengths,
    float*       __restrict__ r_out)
{
    extern __shared__ float smem[];
    float* mem_s = smem;                 // [64][256]
    float* h_s   = smem + Mn * Dn;       // [256]
    float* sc    = h_s + Dn;             // [64] scores -> attn

    const int b    = blockIdx.x;
    const int tid  = threadIdx.x;
    const int lane = tid & 31;
    const int warp = tid >> 5;

    // Load h_tilde[b] and mem[b] (float4, fully coalesced)
    h_s[tid] = h[(size_t)b * Dn + tid];
    const float4* msrc = (const float4*)(mem + (size_t)b * Mn * Dn);
    float4*       mdst = (float4*)mem_s;
#pragma unroll
    for (int i = 0; i < (Mn * Dn / 4) / 256; ++i)
        mdst[tid + 256 * i] = msrc[tid + 256 * i];
    __syncthreads();

    // scores[m] = dot(mem[b,m,:], h[b,:]).  Warp w handles rows w*8..w*8+7.
#pragma unroll
    for (int j = 0; j < 8; ++j) {
        const int m = warp * 8 + j;
        const float* row = mem_s + m * Dn;
        float s = 0.f;
#pragma unroll
        for (int kk = 0; kk < Dn / 32; ++kk)
            s = fmaf(row[lane + 32 * kk], h_s[lane + 32 * kk], s);
#pragma unroll
        for (int off = 16; off; off >>= 1)
            s += __shfl_xor_sync(0xffffffffu, s, off);
        if (lane == 0) sc[m] = s;
    }
    __syncthreads();

    // Masked softmax over 64 slots, done by warp 0 (2 values per lane).
    if (warp == 0) {
        const int len = lengths[b];
        float a0 = (lane      < len) ? sc[lane]      : -1e9f;
        float a1 = (lane + 32 < len) ? sc[lane + 32] : -1e9f;
        float mx = fmaxf(a0, a1);
#pragma unroll
        for (int off = 16; off; off >>= 1)
            mx = fmaxf(mx, __shfl_xor_sync(0xffffffffu, mx, off));
        float e0 = __expf(a0 - mx);
        float e1 = __expf(a1 - mx);
        float s  = e0 + e1;
#pragma unroll
        for (int off = 16; off; off >>= 1)
            s += __shfl_xor_sync(0xffffffffu, s, off);
        const float inv = 1.f / s;
        sc[lane]      = e0 * inv;
        sc[lane + 32] = e1 * inv;
    }
    __syncthreads();

    // r[b,d] = sum_m attn[m] * mem[b,m,d].  Thread tid == d; conflict-free.
    float acc = 0.f;
#pragma unroll
    for (int m = 0; m < Mn; ++m)
        acc = fmaf(sc[m], mem_s[m * Dn + tid], acc);
    r_out[(size_t)b * Dn + tid] = acc;
}

// ---------------------------------------------------------------------------
// Kernel 2: logits = [h|r] @ [Wg|Ug]^T + biases; fused sigmoid/gate epilogue.
// 64x64 tile, 4x4 register blocking, transposed [BK][BM] smem tiles so the
// inner loop reads are LDS.128 conflict-free.
// ---------------------------------------------------------------------------
#define BM 64
#define BN 64
#define BK 16

__global__ __launch_bounds__(256) void gemm_fuse_kernel(
    const float* __restrict__ hA,
    const float* __restrict__ rA,
    const float* __restrict__ Wg,
    const float* __restrict__ Ug,
    const float* __restrict__ Wgb,
    const float* __restrict__ Ugb,
    const float* __restrict__ bg,
    const int*   __restrict__ lengths,
    float*       __restrict__ out)
{
    __shared__ float As[BK][BM];
    __shared__ float Bs[BK][BN];

    const int tid   = threadIdx.x;
    const int tx    = tid & 15;   // col group 0..15
    const int ty    = tid >> 4;   // row group 0..15
    const int rbase = blockIdx.y * BM;
    const int cbase = blockIdx.x * BN;

    const int lr = tid >> 2;        // load row 0..63
    const int lk = (tid & 3) * 4;   // load k   {0,4,8,12}

    float acc[4][4] = {};

    // K = 512 split as 16 tiles from (h, Wg) then 16 tiles from (r, Ug)
#pragma unroll 1
    for (int kt = 0; kt < 32; ++kt) {
        const float* Asrc;
        const float* Bsrc;
        int kbase;
        if (kt < 16) { Asrc = hA; Bsrc = Wg; kbase = kt * 16; }
        else         { Asrc = rA; Bsrc = Ug; kbase = (kt - 16) * 16; }

        const float4 av = *(const float4*)&Asrc[(size_t)(rbase + lr) * Dn + kbase + lk];
        const float4 bv = *(const float4*)&Bsrc[(size_t)(cbase + lr) * Dn + kbase + lk];

        __syncthreads();
        As[lk + 0][lr] = av.x; As[lk + 1][lr] = av.y;
        As[lk + 2][lr] = av.z; As[lk + 3][lr] = av.w;
        Bs[lk + 0][lr] = bv.x; Bs[lk + 1][lr] = bv.y;
        Bs[lk + 2][lr] = bv.z; Bs[lk + 3][lr] = bv.w;
        __syncthreads();

#pragma unroll
        for (int k = 0; k < BK; ++k) {
            const float4 a = *(const float4*)&As[k][ty * 4];
            const float4 b = *(const float4*)&Bs[k][tx * 4];
            const float ar[4] = {a.x, a.y, a.z, a.w};
            const float br[4] = {b.x, b.y, b.z, b.w};
#pragma unroll
            for (int i = 0; i < 4; ++i)
#pragma unroll
                for (int j = 0; j < 4; ++j)
                    acc[i][j] = fmaf(ar[i], br[j], acc[i][j]);
        }
    }

    // Epilogue: bias + sigmoid + gated fusion + empty-memory passthrough.
    float zb[4];
#pragma unroll
    for (int j = 0; j < 4; ++j) {
        const int d = cbase + tx * 4 + j;
        zb[j] = Wgb[d] + Ugb[d] + bg[d];
    }

#pragma unroll
    for (int i = 0; i < 4; ++i) {
        const int b   = rbase + ty * 4 + i;
        const int len = lengths[b];
        const float4 rv = *(const float4*)&rA[(size_t)b * Dn + cbase + tx * 4];
        const float4 hv = *(const float4*)&hA[(size_t)b * Dn + cbase + tx * 4];
        const float rr[4] = {rv.x, rv.y, rv.z, rv.w};
        const float hh[4] = {hv.x, hv.y, hv.z, hv.w};
        float4 o;
        float* op = &o.x;
#pragma unroll
        for (int j = 0; j < 4; ++j) {
            const float z = acc[i][j] + zb[j];
            const float g = 1.f / (1.f + __expf(-z));
            const float fused = g * rr[j] + (1.f - g) * hh[j];
            op[j] = (len > 0) ? fused : hh[j];
        }
        *(float4*)&out[(size_t)b * Dn + cbase + tx * 4] = o;
    }
}

// ---------------------------------------------------------------------------
extern "C" void kernel_launch(void* const* d_in, const int* in_sizes, int n_in,
                              void* d_out, int out_size)
{
    const float* h_tilde = (const float*)d_in[0];
    const float* mem     = (const float*)d_in[1];
    const int*   lengths = (const int*)  d_in[2];
    const float* Wg_w    = (const float*)d_in[3];
    const float* Wg_b    = (const float*)d_in[4];
    const float* Ug_w    = (const float*)d_in[5];
    const float* Ug_b    = (const float*)d_in[6];
    const float* b_g     = (const float*)d_in[7];
    float* out = (float*)d_out;

    float* r_ptr = nullptr;
    cudaGetSymbolAddress((void**)&r_ptr, g_r);

    const int smem_bytes = (Mn * Dn + Dn + Mn) * (int)sizeof(float);
    cudaFuncSetAttribute(attn_kernel,
                         cudaFuncAttributeMaxDynamicSharedMemorySize, smem_bytes);

    attn_kernel<<<Bn, 256, smem_bytes>>>(h_tilde, mem, lengths, r_ptr);

    dim3 grid(Dn / BN, Bn / BM);  // (4, 128)
    gemm_fuse_kernel<<<grid, 256>>>(h_tilde, r_ptr, Wg_w, Ug_w,
                                    Wg_b, Ug_b, b_g, lengths, out);
}